// round 13
// baseline (speedup 1.0000x reference)
#include <cuda_runtime.h>
#include <cuda_bf16.h>
#include <math.h>
#include <stdint.h>

#define NPTS 16384
#define CD   256
#define KHL  512          // hi|lo concatenated K (bf16 elements)
#define TOPK 20
#define CAND 32
#define CHUNK 2048
#define NCHUNK (NPTS/CHUNK)
#define CBUF 512

#define BSROW 72          // smem row stride in bf16 (144 B: ldmatrix conflict-free)
#define BTILE (128*BSROW) // bf16 elements per operand tile
#define TSTRIDE 133       // transpose staging stride (floats)

// -------- scratch (static __device__, no allocations) --------
__device__ float          g_xn [(size_t)NPTS*CD];   // fp32 normalized rows (exact rescore)
__device__ __nv_bfloat16  g_hb [(size_t)NPTS*KHL];  // [:,0:256]=hi bf16, [:,256:512]=lo bf16
__device__ float g_sim [(size_t)NPTS*NPTS];         // full 1 GB similarity
__device__ float g_bmax[(size_t)NPTS*128];          // per-row per-128col-block max
__device__ int   g_idx [NPTS*TOPK];
__device__ float g_Am  [NPTS*CD];
__device__ float g_Bm  [NPTS*CD];
__device__ float g_R   [NPTS*CD];
__device__ float g_hagg[NPTS*CD];
__device__ float g_H   [NPTS*CD];

static __device__ __forceinline__ float4 ld4(const float* p){
    return *reinterpret_cast<const float4*>(p);
}
static __device__ __forceinline__ uint32_t smem_u32(const void* p){
    uint32_t a;
    asm("{ .reg .u64 t; cvta.to.shared.u64 t, %1; cvt.u32.u64 %0, t; }" : "=r"(a) : "l"(p));
    return a;
}

// ================= row normalize + bf16 2-split (hi | lo) =================
__global__ __launch_bounds__(256) void rownorm_split_kernel(const float* __restrict__ x){
    int i = blockIdx.x;
    int t = threadIdx.x;
    float v = x[i*CD + t];
    float s = v*v;
    #pragma unroll
    for (int off=16; off; off>>=1) s += __shfl_xor_sync(0xffffffffu, s, off);
    __shared__ float red[8];
    if ((t & 31) == 0) red[t>>5] = s;
    __syncthreads();
    float tot = red[0]+red[1]+red[2]+red[3]+red[4]+red[5]+red[6]+red[7];
    float rn = 1.0f / fmaxf(sqrtf(tot), 1e-8f);
    float xn = v * rn;
    g_xn[(size_t)i*CD + t] = xn;
    __nv_bfloat16 h = __float2bfloat16(xn);
    float hf = __bfloat162float(h);
    __nv_bfloat16 l = __float2bfloat16(xn - hf);
    g_hb[(size_t)i*KHL + t]       = h;
    g_hb[(size_t)i*KHL + 256 + t] = l;
}

// ================= symmetric sim via mma.sync bf16 + ldmatrix, K=512 ==========
__global__ __launch_bounds__(256,2) void sim_mma_kernel(int cBase)
{
    if (blockIdx.x < blockIdx.y) return;   // J < I: mirror handled by (J,I) tile
    const int I = cBase + blockIdx.y;
    const int J = cBase + blockIdx.x;

    extern __shared__ float smem[];
    __nv_bfloat16* smb = reinterpret_cast<__nv_bfloat16*>(smem);
    const uint32_t smbase = smem_u32(smb);

    const int tid  = threadIdx.x;
    const int warp = tid >> 5, lane = tid & 31;
    const int wr   = warp >> 1;          // 0..3 (m)
    const int wc   = warp & 1;           // 0..1 (n)
    const int g    = lane >> 2;          // 0..7
    const int tg   = lane & 3;           // 0..3
    const int lrow = lane & 15;          // ldmatrix row
    const int lhalf= (lane >> 4) * 8;    // ldmatrix k-half (bf16 elems)

    const __nv_bfloat16* __restrict__ gA = g_hb + (size_t)I * 128 * KHL;
    const __nv_bfloat16* __restrict__ gB = g_hb + (size_t)J * 128 * KHL;

    float acc[2][8][4];
    #pragma unroll
    for (int mi=0;mi<2;mi++)
        #pragma unroll
        for (int nj=0;nj<8;nj++)
            #pragma unroll
            for (int q=0;q<4;q++) acc[mi][nj][q]=0.f;

    const int fr[4] = { (tid + 0)   >> 3, (tid + 256) >> 3, (tid + 512) >> 3, (tid + 768) >> 3 };
    const int col8 = (tid & 7) * 8;      // bf16 column offset (16B granularity)

    #pragma unroll
    for (int p=0;p<4;p++){
        *(float4*)&smb[fr[p]*BSROW + col8]         = ld4((const float*)(gA + (size_t)fr[p]*KHL + col8));
        *(float4*)&smb[BTILE + fr[p]*BSROW + col8] = ld4((const float*)(gB + (size_t)fr[p]*KHL + col8));
    }
    __syncthreads();

    int buf = 0;
    #pragma unroll 1
    for (int kc = 0; kc < 8; kc++){
        float4 va[4], vb[4];
        if (kc < 7){
            const int ko = (kc+1)*64 + col8;
            #pragma unroll
            for (int p=0;p<4;p++){
                va[p] = ld4((const float*)(gA + (size_t)fr[p]*KHL + ko));
                vb[p] = ld4((const float*)(gB + (size_t)fr[p]*KHL + ko));
            }
        }

        const uint32_t Abase = smbase + (uint32_t)(buf*2*BTILE + (wr*32)*BSROW) * 2u;
        const uint32_t Bbase = smbase + (uint32_t)(buf*2*BTILE + BTILE + (wc*64)*BSROW) * 2u;

        #pragma unroll
        for (int ks=0;ks<4;ks++){
            const int kb = ks*16;            // bf16 k offset within chunk
            uint32_t a[2][4];
            #pragma unroll
            for (int mi=0;mi<2;mi++){
                uint32_t addr = Abase + (uint32_t)(((mi*16 + lrow)*BSROW) + kb + lhalf) * 2u;
                asm volatile(
                    "ldmatrix.sync.aligned.m8n8.x4.shared.b16 {%0,%1,%2,%3}, [%4];"
                    : "=r"(a[mi][0]), "=r"(a[mi][1]), "=r"(a[mi][2]), "=r"(a[mi][3])
                    : "r"(addr));
            }
            uint32_t bfrag[4][4];
            #pragma unroll
            for (int njp=0;njp<4;njp++){
                uint32_t addr = Bbase + (uint32_t)(((njp*16 + lrow)*BSROW) + kb + lhalf) * 2u;
                asm volatile(
                    "ldmatrix.sync.aligned.m8n8.x4.shared.b16 {%0,%1,%2,%3}, [%4];"
                    : "=r"(bfrag[njp][0]), "=r"(bfrag[njp][1]),
                      "=r"(bfrag[njp][2]), "=r"(bfrag[njp][3])
                    : "r"(addr));
            }
            #pragma unroll
            for (int nj=0;nj<8;nj++){
                const uint32_t b0 = bfrag[nj>>1][(nj&1)    ];
                const uint32_t b1 = bfrag[nj>>1][(nj&1) + 2];
                #pragma unroll
                for (int mi=0;mi<2;mi++){
                    asm volatile(
                        "mma.sync.aligned.m16n8k16.row.col.f32.bf16.bf16.f32 "
                        "{%0,%1,%2,%3}, {%4,%5,%6,%7}, {%8,%9}, {%0,%1,%2,%3};"
                        : "+f"(acc[mi][nj][0]), "+f"(acc[mi][nj][1]),
                          "+f"(acc[mi][nj][2]), "+f"(acc[mi][nj][3])
                        : "r"(a[mi][0]), "r"(a[mi][1]), "r"(a[mi][2]), "r"(a[mi][3]),
                          "r"(b0), "r"(b1));
                }
            }
        }

        if (kc < 7){
            const int nb = buf ^ 1;
            #pragma unroll
            for (int p=0;p<4;p++){
                *(float4*)&smb[nb*2*BTILE + fr[p]*BSROW + col8]         = va[p];
                *(float4*)&smb[nb*2*BTILE + BTILE + fr[p]*BSROW + col8] = vb[p];
            }
            __syncthreads();
            buf = nb;
        }
    }

    // ================= epilogue =================
    __syncthreads();                        // done with operand tiles: reuse smem
    float* s  = smem;                       // [128][TSTRIDE] transpose staging
    float* sb = smem + 128*TSTRIDE;         // [128][2] row-max staging

    {
        float* C = g_sim + ((size_t)I*128 + wr*32 + g) * NPTS
                         + (size_t)J*128 + wc*64 + 2*tg;
        #pragma unroll
        for (int mi=0;mi<2;mi++){
            #pragma unroll
            for (int nj=0;nj<8;nj++){
                float* c0 = C + (size_t)(mi*16)*NPTS + nj*8;
                *(float2*)c0                     = make_float2(acc[mi][nj][0], acc[mi][nj][1]);
                *(float2*)(c0 + (size_t)8*NPTS)  = make_float2(acc[mi][nj][2], acc[mi][nj][3]);
                const int r0 = wr*32 + mi*16 + g;
                const int c0i = wc*64 + nj*8 + 2*tg;
                s[(r0  )*TSTRIDE + c0i  ] = acc[mi][nj][0];
                s[(r0  )*TSTRIDE + c0i+1] = acc[mi][nj][1];
                s[(r0+8)*TSTRIDE + c0i  ] = acc[mi][nj][2];
                s[(r0+8)*TSTRIDE + c0i+1] = acc[mi][nj][3];
            }
        }
    }

    #pragma unroll
    for (int mi=0;mi<2;mi++){
        float r0 = -1e30f, r1 = -1e30f;
        #pragma unroll
        for (int nj=0;nj<8;nj++){
            r0 = fmaxf(r0, fmaxf(acc[mi][nj][0], acc[mi][nj][1]));
            r1 = fmaxf(r1, fmaxf(acc[mi][nj][2], acc[mi][nj][3]));
        }
        #pragma unroll
        for (int off=1; off<4; off<<=1){
            r0 = fmaxf(r0, __shfl_xor_sync(0xffffffffu, r0, off));
            r1 = fmaxf(r1, __shfl_xor_sync(0xffffffffu, r1, off));
        }
        if (tg == 0){
            sb[(wr*32 + mi*16 + g  )*2 + wc] = r0;
            sb[(wr*32 + mi*16 + g+8)*2 + wc] = r1;
        }
    }
    __syncthreads();
    if (tid < 128){
        float bm = fmaxf(sb[tid*2], sb[tid*2+1]);
        g_bmax[(size_t)(I*128 + tid)*128 + J] = bm;
    }

    if (I != J){
        const int rp = tid >> 1;
        const int cb = (tid & 1) * 64;
        float* CT = g_sim + (size_t)(J*128 + rp) * NPTS + (size_t)I*128 + cb;
        float mx = -1e30f;
        #pragma unroll
        for (int k = 0; k < 16; k++){
            const int c = cb + 4*k;
            float4 v = make_float4(
                s[(c  )*TSTRIDE + rp], s[(c+1)*TSTRIDE + rp],
                s[(c+2)*TSTRIDE + rp], s[(c+3)*TSTRIDE + rp]);
            *(float4*)(CT + 4*k) = v;
            mx = fmaxf(mx, fmaxf(fmaxf(v.x, v.y), fmaxf(v.z, v.w)));
        }
        float o = __shfl_xor_sync(0xffffffffu, mx, 1);
        mx = fmaxf(mx, o);
        if ((tid & 1) == 0)
            g_bmax[(size_t)(J*128 + rp)*128 + I] = mx;
    }
}

// ================= top-20: block-max filter + exact fp32 rescore =================
__global__ __launch_bounds__(256) void topk_kernel(int rowBase)
{
    const int rowG = rowBase + blockIdx.x;
    const float* __restrict__ S  = g_sim  + (size_t)rowG * NPTS;
    const float* __restrict__ BM = g_bmax + (size_t)rowG * 128;
    const int tid = threadIdx.x;
    const int lane = tid & 31, warp = tid >> 5;

    __shared__ float s_tau;
    __shared__ int   s_cnt, s_bcnt;
    __shared__ int   blist[128];
    __shared__ float cv[CBUF];
    __shared__ int   ci[CBUF];
    __shared__ float xi[CD];

    xi[tid] = g_xn[(size_t)rowG*CD + tid];
    if (tid == 0){ s_cnt = 0; s_bcnt = 0; }
    __syncthreads();

    if (warp == 0){
        float a[4];
        #pragma unroll
        for (int j=0;j<4;j++) a[j] = BM[lane*4 + j];
        #define CSW(i,j) { if (a[i] < a[j]) { float t=a[i]; a[i]=a[j]; a[j]=t; } }
        CSW(0,1) CSW(2,3) CSW(0,2) CSW(1,3) CSW(1,2)
        #undef CSW
        float tau = -1e30f;
        for (int sel = 0; sel < CAND; sel++){
            float h = a[0];
            float bv = h;
            #pragma unroll
            for (int off=16; off; off>>=1)
                bv = fmaxf(bv, __shfl_xor_sync(0xffffffffu, bv, off));
            unsigned ball = __ballot_sync(0xffffffffu, h == bv);
            if (lane == (__ffs(ball) - 1)){
                #pragma unroll
                for (int j=0;j<3;j++) a[j] = a[j+1];
                a[3] = -1e30f;
            }
            tau = bv;
        }
        if (lane == 0) s_tau = tau;
    }
    __syncthreads();
    const float tau = s_tau;

    if (tid < 128){
        if (BM[tid] >= tau){ int p = atomicAdd(&s_bcnt, 1); blist[p] = tid; }
    }
    __syncthreads();
    const int bcnt = s_bcnt;

    for (int i = warp; i < bcnt; i += 8){
        const int b = blist[i];
        float4 v = *(const float4*)(S + b*128 + lane*4);
        int base = b*128 + lane*4;
        if (v.x >= tau){ int p = atomicAdd(&s_cnt,1); if (p < CBUF) ci[p] = base+0; }
        if (v.y >= tau){ int p = atomicAdd(&s_cnt,1); if (p < CBUF) ci[p] = base+1; }
        if (v.z >= tau){ int p = atomicAdd(&s_cnt,1); if (p < CBUF) ci[p] = base+2; }
        if (v.w >= tau){ int p = atomicAdd(&s_cnt,1); if (p < CBUF) ci[p] = base+3; }
    }
    __syncthreads();
    int cnt = s_cnt < CBUF ? s_cnt : CBUF;

    for (int p = tid; p < cnt; p += 256){
        const float* __restrict__ xj = g_xn + (size_t)ci[p]*CD;
        float acc = 0.f;
        #pragma unroll 8
        for (int k = 0; k < CD; k++)
            acc = fmaf(xi[k], xj[k], acc);
        cv[p] = acc;
    }
    __syncthreads();

    if (warp == 0){
        for (int sel = 0; sel < TOPK; sel++){
            float bv = -1e30f; int bi = 0x7fffffff; int bp = -1;
            for (int p = lane; p < cnt; p += 32){
                float vv = cv[p]; int ii = ci[p];
                if (vv > bv || (vv == bv && ii < bi)){ bv = vv; bi = ii; bp = p; }
            }
            #pragma unroll
            for (int off=16; off; off>>=1){
                float ov = __shfl_xor_sync(0xffffffffu, bv, off);
                int   oi = __shfl_xor_sync(0xffffffffu, bi, off);
                int   op = __shfl_xor_sync(0xffffffffu, bp, off);
                if (ov > bv || (ov == bv && oi < bi)){ bv = ov; bi = oi; bp = op; }
            }
            if (lane == 0){
                g_idx[(size_t)rowG*TOPK + sel] = bi;
                cv[bp] = -1e30f;
            }
            __syncwarp();
        }
    }
}

// ================= gather + relu + sum over 20 neighbors (banded) =================
__global__ __launch_bounds__(256) void gather_relu_sum_kernel(int rowBase){
    const int i = rowBase + blockIdx.x, c = threadIdx.x;
    __shared__ int nb[TOPK];
    if (c < TOPK) nb[c] = g_idx[(size_t)i*TOPK + c];
    __syncthreads();
    float a = g_Am[(size_t)i*CD + c];
    float acc = 0.f;
    #pragma unroll
    for (int k=0;k<TOPK;k++)
        acc += fmaxf(a + g_Bm[(size_t)nb[k]*CD + c], 0.f);
    g_R[(size_t)i*CD + c] = acc;
}

// ================= generic MLP GEMM (banded rows) =================
__global__ __launch_bounds__(256,2) void mlp_gemm_kernel(
    const float* __restrict__ A1, const float* __restrict__ A2,
    const float* __restrict__ W, int nslab,
    const float* __restrict__ bias, float biasScale,
    int doRelu, const float* __restrict__ res,
    float* __restrict__ Cout, int rowBase128)
{
    __shared__ float As[2][16][132];
    __shared__ float Bs[2][16][132];
    const int tid = threadIdx.x;
    const int r0 = tid >> 2, kq = (tid & 3) << 2;
    const int kr0 = tid >> 5, nq = (tid & 31) << 2;
    const int tx = tid & 15, ty = tid >> 4;
    const int m0 = tx*8, n0 = ty*8;

    const size_t rowOff = (size_t)(rowBase128 + blockIdx.y)*128*CD;
    const float* A1b = A1 + rowOff;
    const float* A2b = A2 ? (A2 + rowOff) : A1b;
    const float* Wb  = W + blockIdx.x*128;

    float acc[8][8];
    #pragma unroll
    for (int i=0;i<8;i++)
        #pragma unroll
        for (int j=0;j<8;j++) acc[i][j]=0.f;

    float4 va0 = ld4(A1b + r0*CD + kq);
    float4 va1 = ld4(A1b + (r0+64)*CD + kq);
    float4 vb0 = ld4(Wb + (size_t)kr0*CD + nq);
    float4 vb1 = ld4(Wb + (size_t)(kr0+8)*CD + nq);

    As[0][kq+0][r0]=va0.x; As[0][kq+1][r0]=va0.y; As[0][kq+2][r0]=va0.z; As[0][kq+3][r0]=va0.w;
    As[0][kq+0][r0+64]=va1.x; As[0][kq+1][r0+64]=va1.y; As[0][kq+2][r0+64]=va1.z; As[0][kq+3][r0+64]=va1.w;
    *(float4*)&Bs[0][kr0  ][nq] = vb0;
    *(float4*)&Bs[0][kr0+8][nq] = vb1;
    __syncthreads();

    int buf = 0;
    for (int s=0; s<nslab; s++){
        if (s+1 < nslab){
            int kk = (s+1)*16;
            const float* Ag = (kk < 256) ? (A1b + kk) : (A2b + (kk-256));
            va0 = ld4(Ag + r0*CD + kq);
            va1 = ld4(Ag + (r0+64)*CD + kq);
            vb0 = ld4(Wb + (size_t)(kk+kr0)*CD + nq);
            vb1 = ld4(Wb + (size_t)(kk+kr0+8)*CD + nq);
        }
        #pragma unroll
        for (int k=0;k<16;k++){
            float4 a0 = *(const float4*)&As[buf][k][m0];
            float4 a1 = *(const float4*)&As[buf][k][m0+4];
            float4 b0 = *(const float4*)&Bs[buf][k][n0];
            float4 b1 = *(const float4*)&Bs[buf][k][n0+4];
            float av[8] = {a0.x,a0.y,a0.z,a0.w,a1.x,a1.y,a1.z,a1.w};
            float bw[8] = {b0.x,b0.y,b0.z,b0.w,b1.x,b1.y,b1.z,b1.w};
            #pragma unroll
            for (int i=0;i<8;i++)
                #pragma unroll
                for (int j=0;j<8;j++)
                    acc[i][j] = fmaf(av[i], bw[j], acc[i][j]);
        }
        if (s+1 < nslab){
            int nb = buf ^ 1;
            As[nb][kq+0][r0]=va0.x; As[nb][kq+1][r0]=va0.y; As[nb][kq+2][r0]=va0.z; As[nb][kq+3][r0]=va0.w;
            As[nb][kq+0][r0+64]=va1.x; As[nb][kq+1][r0+64]=va1.y; As[nb][kq+2][r0+64]=va1.z; As[nb][kq+3][r0+64]=va1.w;
            *(float4*)&Bs[nb][kr0  ][nq] = vb0;
            *(float4*)&Bs[nb][kr0+8][nq] = vb1;
            __syncthreads();
            buf = nb;
        }
    }

    float bv_[8];
    if (bias){
        float4 t0 = ld4(bias + blockIdx.x*128 + n0);
        float4 t1 = ld4(bias + blockIdx.x*128 + n0 + 4);
        bv_[0]=t0.x*biasScale; bv_[1]=t0.y*biasScale; bv_[2]=t0.z*biasScale; bv_[3]=t0.w*biasScale;
        bv_[4]=t1.x*biasScale; bv_[5]=t1.y*biasScale; bv_[6]=t1.z*biasScale; bv_[7]=t1.w*biasScale;
    } else {
        #pragma unroll
        for (int j=0;j<8;j++) bv_[j]=0.f;
    }

    float* Cb = Cout + rowOff + blockIdx.x*128;
    const float* Rb = res ? (res + rowOff + blockIdx.x*128) : nullptr;
    #pragma unroll
    for (int i=0;i<8;i++){
        float o[8];
        #pragma unroll
        for (int j=0;j<8;j++){
            float t = acc[i][j] + bv_[j];
            if (doRelu) t = fmaxf(t, 0.f);
            o[j] = t;
        }
        if (Rb){
            float4 q0 = ld4(Rb + (size_t)(m0+i)*CD + n0);
            float4 q1 = ld4(Rb + (size_t)(m0+i)*CD + n0 + 4);
            o[0]+=q0.x; o[1]+=q0.y; o[2]+=q0.z; o[3]+=q0.w;
            o[4]+=q1.x; o[5]+=q1.y; o[6]+=q1.z; o[7]+=q1.w;
        }
        *(float4*)&Cb[(size_t)(m0+i)*CD + n0  ] = make_float4(o[0],o[1],o[2],o[3]);
        *(float4*)&Cb[(size_t)(m0+i)*CD + n0+4] = make_float4(o[4],o[5],o[6],o[7]);
    }
}

// ================= launch =================
extern "C" void kernel_launch(void* const* d_in, const int* in_sizes, int n_in,
                              void* d_out, int out_size)
{
    const float* x   = (const float*)d_in[0];
    const float* W1m = (const float*)d_in[1];
    const float* b1m = (const float*)d_in[2];
    const float* W2m = (const float*)d_in[3];
    const float* b2m = (const float*)d_in[4];
    const float* W1u = (const float*)d_in[5];
    const float* b1u = (const float*)d_in[6];
    const float* W2u = (const float*)d_in[7];
    const float* b2u = (const float*)d_in[8];
    float* out = (float*)d_out;

    float *p_Am=nullptr, *p_Bm=nullptr, *p_R=nullptr, *p_hagg=nullptr, *p_H=nullptr;
    cudaGetSymbolAddress((void**)&p_Am,   g_Am);
    cudaGetSymbolAddress((void**)&p_Bm,   g_Bm);
    cudaGetSymbolAddress((void**)&p_R,    g_R);
    cudaGetSymbolAddress((void**)&p_hagg, g_hagg);
    cudaGetSymbolAddress((void**)&p_H,    g_H);

    static cudaStream_t s2 = nullptr;
    static cudaEvent_t evSim[NCHUNK], evFork, evLast;
    if (!s2){
        cudaStreamCreateWithFlags(&s2, cudaStreamNonBlocking);
        cudaEventCreateWithFlags(&evFork, cudaEventDisableTiming);
        cudaEventCreateWithFlags(&evLast, cudaEventDisableTiming);
        for (int i = 0; i < NCHUNK; i++)
            cudaEventCreateWithFlags(&evSim[i], cudaEventDisableTiming);
    }

    const int SIM_SMEM = 4 * BTILE * (int)sizeof(__nv_bfloat16);   // 73728 B
    cudaFuncSetAttribute(sim_mma_kernel, cudaFuncAttributeMaxDynamicSharedMemorySize, SIM_SMEM);

    cudaStream_t st = 0;

    rownorm_split_kernel<<<NPTS, 256, 0, st>>>(x);

    // fork s2
    cudaEventRecord(evFork, st);
    cudaStreamWaitEvent(s2, evFork, 0);

    // A_msg / B_msg on s2 (overlap with sim group 0)
    mlp_gemm_kernel<<<dim3(2,128), 256, 0, s2>>>(x, nullptr, W1m,          16, b1m, 1.f, 0, nullptr, p_Am, 0);
    mlp_gemm_kernel<<<dim3(2,128), 256, 0, s2>>>(x, nullptr, W1m + 256*CD, 16, nullptr, 0.f, 0, nullptr, p_Bm, 0);

    // band-ordered symmetric sim (st) + per-band topk+full MLP chain (s2)
    for (int c = 0; c < NCHUNK; c++){
        const int cBase = c * 16;                 // tile-row offset (128-row tiles)
        const int gw = 128 - cBase;               // J range width
        sim_mma_kernel<<<dim3(gw, 16), 256, SIM_SMEM, st>>>(cBase);
        cudaEventRecord(evSim[c], st);
        cudaStreamWaitEvent(s2, evSim[c], 0);

        topk_kernel<<<CHUNK, 256, 0, s2>>>(c*CHUNK);
        gather_relu_sum_kernel<<<CHUNK, 256, 0, s2>>>(c*CHUNK);
        // h_agg[band] = R[band] @ W2_msg + 20*b2_msg
        mlp_gemm_kernel<<<dim3(2,16), 256, 0, s2>>>(p_R, nullptr, W2m, 16, b2m, (float)TOPK, 0, nullptr, p_hagg, cBase);
        // H[band] = relu(x[band]@W1u[0:256] + h_agg[band]@W1u[256:512] + b1u)
        mlp_gemm_kernel<<<dim3(2,16), 256, 0, s2>>>(x, p_hagg, W1u, 32, b1u, 1.f, 1, nullptr, p_H, cBase);
        if (c < NCHUNK-1){
            // out[band] = x[band] + H[band] @ W2_upd + b2_upd
            mlp_gemm_kernel<<<dim3(2,16), 256, 0, s2>>>(p_H, nullptr, W2u, 16, b2u, 1.f, 0, x, out, cBase);
        }
    }

    // join: last band's out-GEMM on the capture stream
    cudaEventRecord(evLast, s2);
    cudaStreamWaitEvent(st, evLast, 0);
    mlp_gemm_kernel<<<dim3(2,16), 256, 0, st>>>(p_H, nullptr, W2u, 16, b2u, 1.f, 0, x, out, (NCHUNK-1)*16);
}

// round 14
// speedup vs baseline: 1.5510x; 1.5510x over previous
#include <cuda_runtime.h>
#include <cuda_bf16.h>
#include <math.h>
#include <stdint.h>

#define NPTS 16384
#define CD   256
#define KHL  512          // hi|lo concatenated K (bf16 elements)
#define TOPK 20
#define CAND 32
#define CHUNK 2048
#define NCHUNK (NPTS/CHUNK)
#define CBUF 512

#define BSROW 72          // smem row stride in bf16 (144 B: ldmatrix conflict-free)
#define BTILE (128*BSROW) // bf16 elements per operand tile
#define TSTRIDE 133       // transpose staging stride (floats)

// -------- scratch (static __device__, no allocations) --------
__device__ float          g_xn [(size_t)NPTS*CD];   // fp32 normalized rows (exact rescore)
__device__ __nv_bfloat16  g_hb [(size_t)NPTS*KHL];  // [:,0:256]=hi bf16, [:,256:512]=lo bf16
__device__ __nv_bfloat16  g_sim[(size_t)NPTS*NPTS]; // 512 MB similarity (bf16, rounded)
__device__ float g_bmax[(size_t)NPTS*128];          // per-row per-128col-block max (of rounded vals)
__device__ int   g_idx [NPTS*TOPK];
__device__ float g_Am  [NPTS*CD];
__device__ float g_Bm  [NPTS*CD];
__device__ float g_R   [NPTS*CD];
__device__ float g_hagg[NPTS*CD];
__device__ float g_H   [NPTS*CD];

static __device__ __forceinline__ float4 ld4(const float* p){
    return *reinterpret_cast<const float4*>(p);
}
static __device__ __forceinline__ uint32_t smem_u32(const void* p){
    uint32_t a;
    asm("{ .reg .u64 t; cvta.to.shared.u64 t, %1; cvt.u32.u64 %0, t; }" : "=r"(a) : "l"(p));
    return a;
}
static __device__ __forceinline__ float bfround(float v){
    return __bfloat162float(__float2bfloat16(v));
}

// ================= row normalize + bf16 2-split (hi | lo) =================
__global__ __launch_bounds__(256) void rownorm_split_kernel(const float* __restrict__ x){
    int i = blockIdx.x;
    int t = threadIdx.x;
    float v = x[i*CD + t];
    float s = v*v;
    #pragma unroll
    for (int off=16; off; off>>=1) s += __shfl_xor_sync(0xffffffffu, s, off);
    __shared__ float red[8];
    if ((t & 31) == 0) red[t>>5] = s;
    __syncthreads();
    float tot = red[0]+red[1]+red[2]+red[3]+red[4]+red[5]+red[6]+red[7];
    float rn = 1.0f / fmaxf(sqrtf(tot), 1e-8f);
    float xn = v * rn;
    g_xn[(size_t)i*CD + t] = xn;
    __nv_bfloat16 h = __float2bfloat16(xn);
    float hf = __bfloat162float(h);
    __nv_bfloat16 l = __float2bfloat16(xn - hf);
    g_hb[(size_t)i*KHL + t]       = h;
    g_hb[(size_t)i*KHL + 256 + t] = l;
}

// ================= symmetric sim via mma.sync bf16 + ldmatrix, K=512 ==========
__global__ __launch_bounds__(256,2) void sim_mma_kernel(int cBase)
{
    if (blockIdx.x < blockIdx.y) return;   // J < I: mirror handled by (J,I) tile
    const int I = cBase + blockIdx.y;
    const int J = cBase + blockIdx.x;

    extern __shared__ float smem[];
    __nv_bfloat16* smb = reinterpret_cast<__nv_bfloat16*>(smem);
    const uint32_t smbase = smem_u32(smb);

    const int tid  = threadIdx.x;
    const int warp = tid >> 5, lane = tid & 31;
    const int wr   = warp >> 1;          // 0..3 (m)
    const int wc   = warp & 1;           // 0..1 (n)
    const int g    = lane >> 2;          // 0..7
    const int tg   = lane & 3;           // 0..3
    const int lrow = lane & 15;          // ldmatrix row
    const int lhalf= (lane >> 4) * 8;    // ldmatrix k-half (bf16 elems)

    const __nv_bfloat16* __restrict__ gA = g_hb + (size_t)I * 128 * KHL;
    const __nv_bfloat16* __restrict__ gB = g_hb + (size_t)J * 128 * KHL;

    float acc[2][8][4];
    #pragma unroll
    for (int mi=0;mi<2;mi++)
        #pragma unroll
        for (int nj=0;nj<8;nj++)
            #pragma unroll
            for (int q=0;q<4;q++) acc[mi][nj][q]=0.f;

    const int fr[4] = { (tid + 0)   >> 3, (tid + 256) >> 3, (tid + 512) >> 3, (tid + 768) >> 3 };
    const int col8 = (tid & 7) * 8;      // bf16 column offset (16B granularity)

    #pragma unroll
    for (int p=0;p<4;p++){
        *(float4*)&smb[fr[p]*BSROW + col8]         = ld4((const float*)(gA + (size_t)fr[p]*KHL + col8));
        *(float4*)&smb[BTILE + fr[p]*BSROW + col8] = ld4((const float*)(gB + (size_t)fr[p]*KHL + col8));
    }
    __syncthreads();

    int buf = 0;
    #pragma unroll 1
    for (int kc = 0; kc < 8; kc++){
        float4 va[4], vb[4];
        if (kc < 7){
            const int ko = (kc+1)*64 + col8;
            #pragma unroll
            for (int p=0;p<4;p++){
                va[p] = ld4((const float*)(gA + (size_t)fr[p]*KHL + ko));
                vb[p] = ld4((const float*)(gB + (size_t)fr[p]*KHL + ko));
            }
        }

        const uint32_t Abase = smbase + (uint32_t)(buf*2*BTILE + (wr*32)*BSROW) * 2u;
        const uint32_t Bbase = smbase + (uint32_t)(buf*2*BTILE + BTILE + (wc*64)*BSROW) * 2u;

        #pragma unroll
        for (int ks=0;ks<4;ks++){
            const int kb = ks*16;
            uint32_t a[2][4];
            #pragma unroll
            for (int mi=0;mi<2;mi++){
                uint32_t addr = Abase + (uint32_t)(((mi*16 + lrow)*BSROW) + kb + lhalf) * 2u;
                asm volatile(
                    "ldmatrix.sync.aligned.m8n8.x4.shared.b16 {%0,%1,%2,%3}, [%4];"
                    : "=r"(a[mi][0]), "=r"(a[mi][1]), "=r"(a[mi][2]), "=r"(a[mi][3])
                    : "r"(addr));
            }
            uint32_t bfrag[4][4];
            #pragma unroll
            for (int njp=0;njp<4;njp++){
                uint32_t addr = Bbase + (uint32_t)(((njp*16 + lrow)*BSROW) + kb + lhalf) * 2u;
                asm volatile(
                    "ldmatrix.sync.aligned.m8n8.x4.shared.b16 {%0,%1,%2,%3}, [%4];"
                    : "=r"(bfrag[njp][0]), "=r"(bfrag[njp][1]),
                      "=r"(bfrag[njp][2]), "=r"(bfrag[njp][3])
                    : "r"(addr));
            }
            #pragma unroll
            for (int nj=0;nj<8;nj++){
                const uint32_t b0 = bfrag[nj>>1][(nj&1)    ];
                const uint32_t b1 = bfrag[nj>>1][(nj&1) + 2];
                #pragma unroll
                for (int mi=0;mi<2;mi++){
                    asm volatile(
                        "mma.sync.aligned.m16n8k16.row.col.f32.bf16.bf16.f32 "
                        "{%0,%1,%2,%3}, {%4,%5,%6,%7}, {%8,%9}, {%0,%1,%2,%3};"
                        : "+f"(acc[mi][nj][0]), "+f"(acc[mi][nj][1]),
                          "+f"(acc[mi][nj][2]), "+f"(acc[mi][nj][3])
                        : "r"(a[mi][0]), "r"(a[mi][1]), "r"(a[mi][2]), "r"(a[mi][3]),
                          "r"(b0), "r"(b1));
                }
            }
        }

        if (kc < 7){
            const int nb = buf ^ 1;
            #pragma unroll
            for (int p=0;p<4;p++){
                *(float4*)&smb[nb*2*BTILE + fr[p]*BSROW + col8]         = va[p];
                *(float4*)&smb[nb*2*BTILE + BTILE + fr[p]*BSROW + col8] = vb[p];
            }
            __syncthreads();
            buf = nb;
        }
    }

    // ================= epilogue =================
    // round accumulators to bf16-representable values FIRST so stored values
    // and block maxima are mutually consistent (monotone rounding -> filter valid)
    #pragma unroll
    for (int mi=0;mi<2;mi++)
        #pragma unroll
        for (int nj=0;nj<8;nj++)
            #pragma unroll
            for (int q=0;q<4;q++) acc[mi][nj][q] = bfround(acc[mi][nj][q]);

    __syncthreads();                        // done with operand tiles: reuse smem
    float* s  = smem;                       // [128][TSTRIDE] transpose staging (rounded fp32)
    float* sb = smem + 128*TSTRIDE;         // [128][2] row-max staging

    // direct bf16 store + stage rounded values
    {
        __nv_bfloat16* C = g_sim + ((size_t)I*128 + wr*32 + g) * NPTS
                                 + (size_t)J*128 + wc*64 + 2*tg;
        #pragma unroll
        for (int mi=0;mi<2;mi++){
            #pragma unroll
            for (int nj=0;nj<8;nj++){
                __nv_bfloat16* c0 = C + (size_t)(mi*16)*NPTS + nj*8;
                *(__nv_bfloat162*)c0 =
                    __nv_bfloat162(__float2bfloat16(acc[mi][nj][0]), __float2bfloat16(acc[mi][nj][1]));
                *(__nv_bfloat162*)(c0 + (size_t)8*NPTS) =
                    __nv_bfloat162(__float2bfloat16(acc[mi][nj][2]), __float2bfloat16(acc[mi][nj][3]));
                const int r0 = wr*32 + mi*16 + g;
                const int c0i = wc*64 + nj*8 + 2*tg;
                s[(r0  )*TSTRIDE + c0i  ] = acc[mi][nj][0];
                s[(r0  )*TSTRIDE + c0i+1] = acc[mi][nj][1];
                s[(r0+8)*TSTRIDE + c0i  ] = acc[mi][nj][2];
                s[(r0+8)*TSTRIDE + c0i+1] = acc[mi][nj][3];
            }
        }
    }

    // per-row tile max (of rounded values) via shuffles
    #pragma unroll
    for (int mi=0;mi<2;mi++){
        float r0 = -1e30f, r1 = -1e30f;
        #pragma unroll
        for (int nj=0;nj<8;nj++){
            r0 = fmaxf(r0, fmaxf(acc[mi][nj][0], acc[mi][nj][1]));
            r1 = fmaxf(r1, fmaxf(acc[mi][nj][2], acc[mi][nj][3]));
        }
        #pragma unroll
        for (int off=1; off<4; off<<=1){
            r0 = fmaxf(r0, __shfl_xor_sync(0xffffffffu, r0, off));
            r1 = fmaxf(r1, __shfl_xor_sync(0xffffffffu, r1, off));
        }
        if (tg == 0){
            sb[(wr*32 + mi*16 + g  )*2 + wc] = r0;
            sb[(wr*32 + mi*16 + g+8)*2 + wc] = r1;
        }
    }
    __syncthreads();
    if (tid < 128){
        float bm = fmaxf(sb[tid*2], sb[tid*2+1]);
        g_bmax[(size_t)(I*128 + tid)*128 + J] = bm;
    }

    // transposed tile (J,I) for off-diagonal (bf16 store, 4 values per 8B)
    if (I != J){
        const int rp = tid >> 1;
        const int cb = (tid & 1) * 64;
        __nv_bfloat16* CT = g_sim + (size_t)(J*128 + rp) * NPTS + (size_t)I*128 + cb;
        float mx = -1e30f;
        #pragma unroll
        for (int k = 0; k < 16; k++){
            const int c = cb + 4*k;
            float v0 = s[(c  )*TSTRIDE + rp];
            float v1 = s[(c+1)*TSTRIDE + rp];
            float v2 = s[(c+2)*TSTRIDE + rp];
            float v3 = s[(c+3)*TSTRIDE + rp];
            __nv_bfloat162 p0(__float2bfloat16(v0), __float2bfloat16(v1));
            __nv_bfloat162 p1(__float2bfloat16(v2), __float2bfloat16(v3));
            uint2 pk;
            pk.x = *(uint32_t*)&p0; pk.y = *(uint32_t*)&p1;
            *(uint2*)(CT + 4*k) = pk;
            mx = fmaxf(mx, fmaxf(fmaxf(v0, v1), fmaxf(v2, v3)));
        }
        float o = __shfl_xor_sync(0xffffffffu, mx, 1);
        mx = fmaxf(mx, o);
        if ((tid & 1) == 0)
            g_bmax[(size_t)(J*128 + rp)*128 + I] = mx;
    }
}

// ================= top-20: block-max filter + exact fp32 rescore =================
__global__ __launch_bounds__(256) void topk_kernel(int rowBase)
{
    const int rowG = rowBase + blockIdx.x;
    const __nv_bfloat16* __restrict__ S = g_sim + (size_t)rowG * NPTS;
    const float* __restrict__ BM = g_bmax + (size_t)rowG * 128;
    const int tid = threadIdx.x;
    const int lane = tid & 31, warp = tid >> 5;

    __shared__ float s_tau;
    __shared__ int   s_cnt, s_bcnt;
    __shared__ int   blist[128];
    __shared__ float cv[CBUF];
    __shared__ int   ci[CBUF];
    __shared__ float xi[CD];

    xi[tid] = g_xn[(size_t)rowG*CD + tid];
    if (tid == 0){ s_cnt = 0; s_bcnt = 0; }
    __syncthreads();

    // tau = CAND-th largest of the 128 block maxima (valid top-CAND filter)
    if (warp == 0){
        float a[4];
        #pragma unroll
        for (int j=0;j<4;j++) a[j] = BM[lane*4 + j];
        #define CSW(i,j) { if (a[i] < a[j]) { float t=a[i]; a[i]=a[j]; a[j]=t; } }
        CSW(0,1) CSW(2,3) CSW(0,2) CSW(1,3) CSW(1,2)
        #undef CSW
        float tau = -1e30f;
        for (int sel = 0; sel < CAND; sel++){
            float h = a[0];
            float bv = h;
            #pragma unroll
            for (int off=16; off; off>>=1)
                bv = fmaxf(bv, __shfl_xor_sync(0xffffffffu, bv, off));
            unsigned ball = __ballot_sync(0xffffffffu, h == bv);
            if (lane == (__ffs(ball) - 1)){
                #pragma unroll
                for (int j=0;j<3;j++) a[j] = a[j+1];
                a[3] = -1e30f;
            }
            tau = bv;
        }
        if (lane == 0) s_tau = tau;
    }
    __syncthreads();
    const float tau = s_tau;

    if (tid < 128){
        if (BM[tid] >= tau){ int p = atomicAdd(&s_bcnt, 1); blist[p] = tid; }
    }
    __syncthreads();
    const int bcnt = s_bcnt;

    // collect candidates: one warp per qualifying block, 4 bf16 per lane
    for (int i = warp; i < bcnt; i += 8){
        const int b = blist[i];
        uint2 pk = *(const uint2*)(S + b*128 + lane*4);
        __nv_bfloat162 p0 = *(__nv_bfloat162*)&pk.x;
        __nv_bfloat162 p1 = *(__nv_bfloat162*)&pk.y;
        float vx = __bfloat162float(p0.x), vy = __bfloat162float(p0.y);
        float vz = __bfloat162float(p1.x), vw = __bfloat162float(p1.y);
        int base = b*128 + lane*4;
        if (vx >= tau){ int p = atomicAdd(&s_cnt,1); if (p < CBUF) ci[p] = base+0; }
        if (vy >= tau){ int p = atomicAdd(&s_cnt,1); if (p < CBUF) ci[p] = base+1; }
        if (vz >= tau){ int p = atomicAdd(&s_cnt,1); if (p < CBUF) ci[p] = base+2; }
        if (vw >= tau){ int p = atomicAdd(&s_cnt,1); if (p < CBUF) ci[p] = base+3; }
    }
    __syncthreads();
    int cnt = s_cnt < CBUF ? s_cnt : CBUF;

    // exact fp32 rescore (serial k-ascending fmaf — matches reference selections)
    for (int p = tid; p < cnt; p += 256){
        const float* __restrict__ xj = g_xn + (size_t)ci[p]*CD;
        float acc = 0.f;
        #pragma unroll 8
        for (int k = 0; k < CD; k++)
            acc = fmaf(xi[k], xj[k], acc);
        cv[p] = acc;
    }
    __syncthreads();

    // warp 0 selects top-20 by exact values (tie-break: lowest index)
    if (warp == 0){
        for (int sel = 0; sel < TOPK; sel++){
            float bv = -1e30f; int bi = 0x7fffffff; int bp = -1;
            for (int p = lane; p < cnt; p += 32){
                float vv = cv[p]; int ii = ci[p];
                if (vv > bv || (vv == bv && ii < bi)){ bv = vv; bi = ii; bp = p; }
            }
            #pragma unroll
            for (int off=16; off; off>>=1){
                float ov = __shfl_xor_sync(0xffffffffu, bv, off);
                int   oi = __shfl_xor_sync(0xffffffffu, bi, off);
                int   op = __shfl_xor_sync(0xffffffffu, bp, off);
                if (ov > bv || (ov == bv && oi < bi)){ bv = ov; bi = oi; bp = op; }
            }
            if (lane == 0){
                g_idx[(size_t)rowG*TOPK + sel] = bi;
                cv[bp] = -1e30f;
            }
            __syncwarp();
        }
    }
}

// ================= gather + relu + sum over 20 neighbors =================
__global__ __launch_bounds__(256) void gather_relu_sum_kernel(){
    const int i = blockIdx.x, c = threadIdx.x;
    __shared__ int nb[TOPK];
    if (c < TOPK) nb[c] = g_idx[(size_t)i*TOPK + c];
    __syncthreads();
    float a = g_Am[(size_t)i*CD + c];
    float acc = 0.f;
    #pragma unroll
    for (int k=0;k<TOPK;k++)
        acc += fmaxf(a + g_Bm[(size_t)nb[k]*CD + c], 0.f);
    g_R[(size_t)i*CD + c] = acc;
}

// ================= generic MLP GEMM =================
__global__ __launch_bounds__(256,2) void mlp_gemm_kernel(
    const float* __restrict__ A1, const float* __restrict__ A2,
    const float* __restrict__ W, int nslab,
    const float* __restrict__ bias, float biasScale,
    int doRelu, const float* __restrict__ res,
    float* __restrict__ Cout)
{
    __shared__ float As[2][16][132];
    __shared__ float Bs[2][16][132];
    const int tid = threadIdx.x;
    const int r0 = tid >> 2, kq = (tid & 3) << 2;
    const int kr0 = tid >> 5, nq = (tid & 31) << 2;
    const int tx = tid & 15, ty = tid >> 4;
    const int m0 = tx*8, n0 = ty*8;

    const size_t rowOff = (size_t)blockIdx.y*128*CD;
    const float* A1b = A1 + rowOff;
    const float* A2b = A2 ? (A2 + rowOff) : A1b;
    const float* Wb  = W + blockIdx.x*128;

    float acc[8][8];
    #pragma unroll
    for (int i=0;i<8;i++)
        #pragma unroll
        for (int j=0;j<8;j++) acc[i][j]=0.f;

    float4 va0 = ld4(A1b + r0*CD + kq);
    float4 va1 = ld4(A1b + (r0+64)*CD + kq);
    float4 vb0 = ld4(Wb + (size_t)kr0*CD + nq);
    float4 vb1 = ld4(Wb + (size_t)(kr0+8)*CD + nq);

    As[0][kq+0][r0]=va0.x; As[0][kq+1][r0]=va0.y; As[0][kq+2][r0]=va0.z; As[0][kq+3][r0]=va0.w;
    As[0][kq+0][r0+64]=va1.x; As[0][kq+1][r0+64]=va1.y; As[0][kq+2][r0+64]=va1.z; As[0][kq+3][r0+64]=va1.w;
    *(float4*)&Bs[0][kr0  ][nq] = vb0;
    *(float4*)&Bs[0][kr0+8][nq] = vb1;
    __syncthreads();

    int buf = 0;
    for (int s=0; s<nslab; s++){
        if (s+1 < nslab){
            int kk = (s+1)*16;
            const float* Ag = (kk < 256) ? (A1b + kk) : (A2b + (kk-256));
            va0 = ld4(Ag + r0*CD + kq);
            va1 = ld4(Ag + (r0+64)*CD + kq);
            vb0 = ld4(Wb + (size_t)(kk+kr0)*CD + nq);
            vb1 = ld4(Wb + (size_t)(kk+kr0+8)*CD + nq);
        }
        #pragma unroll
        for (int k=0;k<16;k++){
            float4 a0 = *(const float4*)&As[buf][k][m0];
            float4 a1 = *(const float4*)&As[buf][k][m0+4];
            float4 b0 = *(const float4*)&Bs[buf][k][n0];
            float4 b1 = *(const float4*)&Bs[buf][k][n0+4];
            float av[8] = {a0.x,a0.y,a0.z,a0.w,a1.x,a1.y,a1.z,a1.w};
            float bw[8] = {b0.x,b0.y,b0.z,b0.w,b1.x,b1.y,b1.z,b1.w};
            #pragma unroll
            for (int i=0;i<8;i++)
                #pragma unroll
                for (int j=0;j<8;j++)
                    acc[i][j] = fmaf(av[i], bw[j], acc[i][j]);
        }
        if (s+1 < nslab){
            int nb = buf ^ 1;
            As[nb][kq+0][r0]=va0.x; As[nb][kq+1][r0]=va0.y; As[nb][kq+2][r0]=va0.z; As[nb][kq+3][r0]=va0.w;
            As[nb][kq+0][r0+64]=va1.x; As[nb][kq+1][r0+64]=va1.y; As[nb][kq+2][r0+64]=va1.z; As[nb][kq+3][r0+64]=va1.w;
            *(float4*)&Bs[nb][kr0  ][nq] = vb0;
            *(float4*)&Bs[nb][kr0+8][nq] = vb1;
            __syncthreads();
            buf = nb;
        }
    }

    float bv_[8];
    if (bias){
        float4 t0 = ld4(bias + blockIdx.x*128 + n0);
        float4 t1 = ld4(bias + blockIdx.x*128 + n0 + 4);
        bv_[0]=t0.x*biasScale; bv_[1]=t0.y*biasScale; bv_[2]=t0.z*biasScale; bv_[3]=t0.w*biasScale;
        bv_[4]=t1.x*biasScale; bv_[5]=t1.y*biasScale; bv_[6]=t1.z*biasScale; bv_[7]=t1.w*biasScale;
    } else {
        #pragma unroll
        for (int j=0;j<8;j++) bv_[j]=0.f;
    }

    float* Cb = Cout + (size_t)blockIdx.y*128*CD + blockIdx.x*128;
    const float* Rb = res ? (res + (size_t)blockIdx.y*128*CD + blockIdx.x*128) : nullptr;
    #pragma unroll
    for (int i=0;i<8;i++){
        float o[8];
        #pragma unroll
        for (int j=0;j<8;j++){
            float t = acc[i][j] + bv_[j];
            if (doRelu) t = fmaxf(t, 0.f);
            o[j] = t;
        }
        if (Rb){
            float4 q0 = ld4(Rb + (size_t)(m0+i)*CD + n0);
            float4 q1 = ld4(Rb + (size_t)(m0+i)*CD + n0 + 4);
            o[0]+=q0.x; o[1]+=q0.y; o[2]+=q0.z; o[3]+=q0.w;
            o[4]+=q1.x; o[5]+=q1.y; o[6]+=q1.z; o[7]+=q1.w;
        }
        *(float4*)&Cb[(size_t)(m0+i)*CD + n0  ] = make_float4(o[0],o[1],o[2],o[3]);
        *(float4*)&Cb[(size_t)(m0+i)*CD + n0+4] = make_float4(o[4],o[5],o[6],o[7]);
    }
}

// ================= launch =================
extern "C" void kernel_launch(void* const* d_in, const int* in_sizes, int n_in,
                              void* d_out, int out_size)
{
    const float* x   = (const float*)d_in[0];
    const float* W1m = (const float*)d_in[1];
    const float* b1m = (const float*)d_in[2];
    const float* W2m = (const float*)d_in[3];
    const float* b2m = (const float*)d_in[4];
    const float* W1u = (const float*)d_in[5];
    const float* b1u = (const float*)d_in[6];
    const float* W2u = (const float*)d_in[7];
    const float* b2u = (const float*)d_in[8];
    float* out = (float*)d_out;

    float *p_Am=nullptr, *p_Bm=nullptr, *p_R=nullptr, *p_hagg=nullptr, *p_H=nullptr;
    cudaGetSymbolAddress((void**)&p_Am,   g_Am);
    cudaGetSymbolAddress((void**)&p_Bm,   g_Bm);
    cudaGetSymbolAddress((void**)&p_R,    g_R);
    cudaGetSymbolAddress((void**)&p_hagg, g_hagg);
    cudaGetSymbolAddress((void**)&p_H,    g_H);

    static cudaStream_t s2 = nullptr;
    static cudaEvent_t evSim[NCHUNK], evTk[NCHUNK], evFork;
    if (!s2){
        cudaStreamCreateWithFlags(&s2, cudaStreamNonBlocking);
        cudaEventCreateWithFlags(&evFork, cudaEventDisableTiming);
        for (int i = 0; i < NCHUNK; i++){
            cudaEventCreateWithFlags(&evSim[i], cudaEventDisableTiming);
            cudaEventCreateWithFlags(&evTk[i],  cudaEventDisableTiming);
        }
    }

    const int SIM_SMEM = 4 * BTILE * (int)sizeof(__nv_bfloat16);   // 73728 B
    cudaFuncSetAttribute(sim_mma_kernel, cudaFuncAttributeMaxDynamicSharedMemorySize, SIM_SMEM);

    cudaStream_t st = 0;

    rownorm_split_kernel<<<NPTS, 256, 0, st>>>(x);

    // fork s2
    cudaEventRecord(evFork, st);
    cudaStreamWaitEvent(s2, evFork, 0);

    // A_msg / B_msg on s2 (overlap with sim)
    mlp_gemm_kernel<<<dim3(2,128), 256, 0, s2>>>(x, nullptr, W1m,          16, b1m, 1.f, 0, nullptr, p_Am);
    mlp_gemm_kernel<<<dim3(2,128), 256, 0, s2>>>(x, nullptr, W1m + 256*CD, 16, nullptr, 0.f, 0, nullptr, p_Bm);

    // band-ordered symmetric sim (st) + per-band topk (s2)
    for (int c = 0; c < NCHUNK; c++){
        const int cBase = c * 16;                 // tile-row offset (128-row tiles)
        const int gw = 128 - cBase;               // J range width
        sim_mma_kernel<<<dim3(gw, 16), 256, SIM_SMEM, st>>>(cBase);
        cudaEventRecord(evSim[c], st);
        cudaStreamWaitEvent(s2, evSim[c], 0);
        topk_kernel<<<CHUNK, 256, 0, s2>>>(c*CHUNK);
        cudaEventRecord(evTk[c], s2);
    }
    cudaStreamWaitEvent(st, evTk[NCHUNK-1], 0);

    // R_i = sum_j relu(A_i + B_j)
    gather_relu_sum_kernel<<<NPTS, 256, 0, st>>>();

    // h_agg = R @ W2_msg + 20*b2_msg
    mlp_gemm_kernel<<<dim3(2,128), 256, 0, st>>>(p_R, nullptr, W2m, 16, b2m, (float)TOPK, 0, nullptr, p_hagg);

    // H = relu(x @ W1u[0:256] + h_agg @ W1u[256:512] + b1u)
    mlp_gemm_kernel<<<dim3(2,128), 256, 0, st>>>(x, p_hagg, W1u, 32, b1u, 1.f, 1, nullptr, p_H);

    // out = x + H @ W2_upd + b2_upd
    mlp_gemm_kernel<<<dim3(2,128), 256, 0, st>>>(p_H, nullptr, W2u, 16, b2u, 1.f, 0, x, out);
}

// round 16
// speedup vs baseline: 1.9373x; 1.2490x over previous
#include <cuda_runtime.h>
#include <cuda_bf16.h>
#include <math.h>
#include <stdint.h>

#define NPTS 16384
#define CD   256
#define KHL  512          // hi|lo concatenated K (bf16 elements)
#define TOPK 20
#define CAND 32
#define CHUNK 2048
#define NCHUNK (NPTS/CHUNK)
#define CBUF 512
#define SBLK 64           // max staged candidate blocks

#define BSROW 72          // smem row stride in bf16 (144 B: ldmatrix conflict-free)
#define BTILE (128*BSROW) // bf16 elements per operand tile
#define TSTRIDE 133       // transpose staging stride (floats)

// -------- scratch (static __device__, no allocations) --------
__device__ float          g_xn [(size_t)NPTS*CD];   // fp32 normalized rows (exact rescore)
__device__ __nv_bfloat16  g_hb [(size_t)NPTS*KHL];  // [:,0:256]=hi bf16, [:,256:512]=lo bf16
__device__ __nv_bfloat16  g_sim[(size_t)NPTS*NPTS]; // 512 MB similarity (bf16, rounded)
__device__ float g_bmax[(size_t)NPTS*128];          // per-row per-128col-block max (of rounded vals)
__device__ int   g_idx [NPTS*TOPK];
__device__ float g_Am  [NPTS*CD];
__device__ float g_Bm  [NPTS*CD];
__device__ float g_R   [NPTS*CD];
__device__ float g_hagg[NPTS*CD];
__device__ float g_H   [NPTS*CD];

static __device__ __forceinline__ float4 ld4(const float* p){
    return *reinterpret_cast<const float4*>(p);
}
static __device__ __forceinline__ uint32_t smem_u32(const void* p){
    uint32_t a;
    asm("{ .reg .u64 t; cvta.to.shared.u64 t, %1; cvt.u32.u64 %0, t; }" : "=r"(a) : "l"(p));
    return a;
}
static __device__ __forceinline__ float bfround(float v){
    return __bfloat162float(__float2bfloat16(v));
}

// ================= row normalize + bf16 2-split (hi | lo) =================
__global__ __launch_bounds__(256) void rownorm_split_kernel(const float* __restrict__ x){
    int i = blockIdx.x;
    int t = threadIdx.x;
    float v = x[i*CD + t];
    float s = v*v;
    #pragma unroll
    for (int off=16; off; off>>=1) s += __shfl_xor_sync(0xffffffffu, s, off);
    __shared__ float red[8];
    if ((t & 31) == 0) red[t>>5] = s;
    __syncthreads();
    float tot = red[0]+red[1]+red[2]+red[3]+red[4]+red[5]+red[6]+red[7];
    float rn = 1.0f / fmaxf(sqrtf(tot), 1e-8f);
    float xn = v * rn;
    g_xn[(size_t)i*CD + t] = xn;
    __nv_bfloat16 h = __float2bfloat16(xn);
    float hf = __bfloat162float(h);
    __nv_bfloat16 l = __float2bfloat16(xn - hf);
    g_hb[(size_t)i*KHL + t]       = h;
    g_hb[(size_t)i*KHL + 256 + t] = l;
}

// ================= symmetric sim via mma.sync bf16 + ldmatrix, K=512 ==========
__global__ __launch_bounds__(256,2) void sim_mma_kernel(int cBase)
{
    if (blockIdx.x < blockIdx.y) return;   // J < I: mirror handled by (J,I) tile
    const int I = cBase + blockIdx.y;
    const int J = cBase + blockIdx.x;

    extern __shared__ float smem[];
    __nv_bfloat16* smb = reinterpret_cast<__nv_bfloat16*>(smem);
    const uint32_t smbase = smem_u32(smb);

    const int tid  = threadIdx.x;
    const int warp = tid >> 5, lane = tid & 31;
    const int wr   = warp >> 1;          // 0..3 (m)
    const int wc   = warp & 1;           // 0..1 (n)
    const int g    = lane >> 2;          // 0..7
    const int tg   = lane & 3;           // 0..3
    const int lrow = lane & 15;          // ldmatrix row
    const int lhalf= (lane >> 4) * 8;    // ldmatrix k-half (bf16 elems)

    const __nv_bfloat16* __restrict__ gA = g_hb + (size_t)I * 128 * KHL;
    const __nv_bfloat16* __restrict__ gB = g_hb + (size_t)J * 128 * KHL;

    float acc[2][8][4];
    #pragma unroll
    for (int mi=0;mi<2;mi++)
        #pragma unroll
        for (int nj=0;nj<8;nj++)
            #pragma unroll
            for (int q=0;q<4;q++) acc[mi][nj][q]=0.f;

    const int fr[4] = { (tid + 0)   >> 3, (tid + 256) >> 3, (tid + 512) >> 3, (tid + 768) >> 3 };
    const int col8 = (tid & 7) * 8;      // bf16 column offset (16B granularity)

    #pragma unroll
    for (int p=0;p<4;p++){
        *(float4*)&smb[fr[p]*BSROW + col8]         = ld4((const float*)(gA + (size_t)fr[p]*KHL + col8));
        *(float4*)&smb[BTILE + fr[p]*BSROW + col8] = ld4((const float*)(gB + (size_t)fr[p]*KHL + col8));
    }
    __syncthreads();

    int buf = 0;
    #pragma unroll 1
    for (int kc = 0; kc < 8; kc++){
        float4 va[4], vb[4];
        if (kc < 7){
            const int ko = (kc+1)*64 + col8;
            #pragma unroll
            for (int p=0;p<4;p++){
                va[p] = ld4((const float*)(gA + (size_t)fr[p]*KHL + ko));
                vb[p] = ld4((const float*)(gB + (size_t)fr[p]*KHL + ko));
            }
        }

        const uint32_t Abase = smbase + (uint32_t)(buf*2*BTILE + (wr*32)*BSROW) * 2u;
        const uint32_t Bbase = smbase + (uint32_t)(buf*2*BTILE + BTILE + (wc*64)*BSROW) * 2u;

        #pragma unroll
        for (int ks=0;ks<4;ks++){
            const int kb = ks*16;
            uint32_t a[2][4];
            #pragma unroll
            for (int mi=0;mi<2;mi++){
                uint32_t addr = Abase + (uint32_t)(((mi*16 + lrow)*BSROW) + kb + lhalf) * 2u;
                asm volatile(
                    "ldmatrix.sync.aligned.m8n8.x4.shared.b16 {%0,%1,%2,%3}, [%4];"
                    : "=r"(a[mi][0]), "=r"(a[mi][1]), "=r"(a[mi][2]), "=r"(a[mi][3])
                    : "r"(addr));
            }
            uint32_t bfrag[4][4];
            #pragma unroll
            for (int njp=0;njp<4;njp++){
                uint32_t addr = Bbase + (uint32_t)(((njp*16 + lrow)*BSROW) + kb + lhalf) * 2u;
                asm volatile(
                    "ldmatrix.sync.aligned.m8n8.x4.shared.b16 {%0,%1,%2,%3}, [%4];"
                    : "=r"(bfrag[njp][0]), "=r"(bfrag[njp][1]),
                      "=r"(bfrag[njp][2]), "=r"(bfrag[njp][3])
                    : "r"(addr));
            }
            #pragma unroll
            for (int nj=0;nj<8;nj++){
                const uint32_t b0 = bfrag[nj>>1][(nj&1)    ];
                const uint32_t b1 = bfrag[nj>>1][(nj&1) + 2];
                #pragma unroll
                for (int mi=0;mi<2;mi++){
                    asm volatile(
                        "mma.sync.aligned.m16n8k16.row.col.f32.bf16.bf16.f32 "
                        "{%0,%1,%2,%3}, {%4,%5,%6,%7}, {%8,%9}, {%0,%1,%2,%3};"
                        : "+f"(acc[mi][nj][0]), "+f"(acc[mi][nj][1]),
                          "+f"(acc[mi][nj][2]), "+f"(acc[mi][nj][3])
                        : "r"(a[mi][0]), "r"(a[mi][1]), "r"(a[mi][2]), "r"(a[mi][3]),
                          "r"(b0), "r"(b1));
                }
            }
        }

        if (kc < 7){
            const int nb = buf ^ 1;
            #pragma unroll
            for (int p=0;p<4;p++){
                *(float4*)&smb[nb*2*BTILE + fr[p]*BSROW + col8]         = va[p];
                *(float4*)&smb[nb*2*BTILE + BTILE + fr[p]*BSROW + col8] = vb[p];
            }
            __syncthreads();
            buf = nb;
        }
    }

    // ================= epilogue =================
    #pragma unroll
    for (int mi=0;mi<2;mi++)
        #pragma unroll
        for (int nj=0;nj<8;nj++)
            #pragma unroll
            for (int q=0;q<4;q++) acc[mi][nj][q] = bfround(acc[mi][nj][q]);

    __syncthreads();
    float* s  = smem;                       // [128][TSTRIDE] transpose staging (rounded fp32)
    float* sb = smem + 128*TSTRIDE;         // [128][2] row-max staging

    {
        __nv_bfloat16* C = g_sim + ((size_t)I*128 + wr*32 + g) * NPTS
                                 + (size_t)J*128 + wc*64 + 2*tg;
        #pragma unroll
        for (int mi=0;mi<2;mi++){
            #pragma unroll
            for (int nj=0;nj<8;nj++){
                __nv_bfloat16* c0 = C + (size_t)(mi*16)*NPTS + nj*8;
                *(__nv_bfloat162*)c0 =
                    __nv_bfloat162(__float2bfloat16(acc[mi][nj][0]), __float2bfloat16(acc[mi][nj][1]));
                *(__nv_bfloat162*)(c0 + (size_t)8*NPTS) =
                    __nv_bfloat162(__float2bfloat16(acc[mi][nj][2]), __float2bfloat16(acc[mi][nj][3]));
                const int r0 = wr*32 + mi*16 + g;
                const int c0i = wc*64 + nj*8 + 2*tg;
                s[(r0  )*TSTRIDE + c0i  ] = acc[mi][nj][0];
                s[(r0  )*TSTRIDE + c0i+1] = acc[mi][nj][1];
                s[(r0+8)*TSTRIDE + c0i  ] = acc[mi][nj][2];
                s[(r0+8)*TSTRIDE + c0i+1] = acc[mi][nj][3];
            }
        }
    }

    #pragma unroll
    for (int mi=0;mi<2;mi++){
        float r0 = -1e30f, r1 = -1e30f;
        #pragma unroll
        for (int nj=0;nj<8;nj++){
            r0 = fmaxf(r0, fmaxf(acc[mi][nj][0], acc[mi][nj][1]));
            r1 = fmaxf(r1, fmaxf(acc[mi][nj][2], acc[mi][nj][3]));
        }
        #pragma unroll
        for (int off=1; off<4; off<<=1){
            r0 = fmaxf(r0, __shfl_xor_sync(0xffffffffu, r0, off));
            r1 = fmaxf(r1, __shfl_xor_sync(0xffffffffu, r1, off));
        }
        if (tg == 0){
            sb[(wr*32 + mi*16 + g  )*2 + wc] = r0;
            sb[(wr*32 + mi*16 + g+8)*2 + wc] = r1;
        }
    }
    __syncthreads();
    if (tid < 128){
        float bm = fmaxf(sb[tid*2], sb[tid*2+1]);
        g_bmax[(size_t)(I*128 + tid)*128 + J] = bm;
    }

    if (I != J){
        const int rp = tid >> 1;
        const int cb = (tid & 1) * 64;
        __nv_bfloat16* CT = g_sim + (size_t)(J*128 + rp) * NPTS + (size_t)I*128 + cb;
        float mx = -1e30f;
        #pragma unroll
        for (int k = 0; k < 16; k++){
            const int c = cb + 4*k;
            float v0 = s[(c  )*TSTRIDE + rp];
            float v1 = s[(c+1)*TSTRIDE + rp];
            float v2 = s[(c+2)*TSTRIDE + rp];
            float v3 = s[(c+3)*TSTRIDE + rp];
            __nv_bfloat162 p0(__float2bfloat16(v0), __float2bfloat16(v1));
            __nv_bfloat162 p1(__float2bfloat16(v2), __float2bfloat16(v3));
            uint2 pk;
            pk.x = *(uint32_t*)&p0; pk.y = *(uint32_t*)&p1;
            *(uint2*)(CT + 4*k) = pk;
            mx = fmaxf(mx, fmaxf(fmaxf(v0, v1), fmaxf(v2, v3)));
        }
        float o = __shfl_xor_sync(0xffffffffu, mx, 1);
        mx = fmaxf(mx, o);
        if ((tid & 1) == 0)
            g_bmax[(size_t)(J*128 + rp)*128 + I] = mx;
    }
}

// ================= top-20: block-max filter + staged collect + exact rescore =====
__global__ __launch_bounds__(256) void topk_kernel(int rowBase)
{
    const int rowG = rowBase + blockIdx.x;
    const __nv_bfloat16* __restrict__ S = g_sim + (size_t)rowG * NPTS;
    const float* __restrict__ BM = g_bmax + (size_t)rowG * 128;
    const int tid = threadIdx.x;
    const int lane = tid & 31, warp = tid >> 5;

    __shared__ float s_tau;
    __shared__ int   s_cnt, s_bcnt;
    __shared__ int   blist[128];
    __shared__ __align__(16) __nv_bfloat16 sv[SBLK*128];   // staged blocks (16 KB)
    __shared__ float cv[CBUF];
    __shared__ int   ci[CBUF];
    __shared__ float xi[CD];

    xi[tid] = g_xn[(size_t)rowG*CD + tid];
    if (tid == 0){ s_cnt = 0; s_bcnt = 0; }
    __syncthreads();

    // tau = CAND-th largest of the 128 block maxima (valid top-CAND filter)
    if (warp == 0){
        float a[4];
        #pragma unroll
        for (int j=0;j<4;j++) a[j] = BM[lane*4 + j];
        #define CSW(i,j) { if (a[i] < a[j]) { float t=a[i]; a[i]=a[j]; a[j]=t; } }
        CSW(0,1) CSW(2,3) CSW(0,2) CSW(1,3) CSW(1,2)
        #undef CSW
        float tau = -1e30f;
        for (int sel = 0; sel < CAND; sel++){
            float h = a[0];
            float bv = h;
            #pragma unroll
            for (int off=16; off; off>>=1)
                bv = fmaxf(bv, __shfl_xor_sync(0xffffffffu, bv, off));
            unsigned ball = __ballot_sync(0xffffffffu, h == bv);
            if (lane == (__ffs(ball) - 1)){
                #pragma unroll
                for (int j=0;j<3;j++) a[j] = a[j+1];
                a[3] = -1e30f;
            }
            tau = bv;
        }
        if (lane == 0) s_tau = tau;
    }
    __syncthreads();
    const float tau = s_tau;

    if (tid < 128){
        if (BM[tid] >= tau){ int p = atomicAdd(&s_bcnt, 1); blist[p] = tid; }
    }
    __syncthreads();
    const int bcnt = s_bcnt < SBLK ? s_bcnt : SBLK;

    // stage qualifying blocks into smem: each warp handles 4 blocks per pass,
    // all loads issued independently before stores (latency overlap)
    for (int i0 = warp; i0 < bcnt; i0 += 32){
        uint2 pk[4];
        int  idx[4];
        #pragma unroll
        for (int q=0;q<4;q++){
            int i = i0 + 8*q;
            idx[q] = (i < bcnt) ? i : -1;
            if (idx[q] >= 0)
                pk[q] = *(const uint2*)(S + blist[i]*128 + lane*4);
        }
        #pragma unroll
        for (int q=0;q<4;q++){
            if (idx[q] >= 0)
                *(uint2*)&sv[idx[q]*128 + lane*4] = pk[q];
        }
    }
    __syncthreads();

    // filter from smem
    for (int e = tid; e < bcnt*128; e += 256){
        float v = __bfloat162float(sv[e]);
        if (v >= tau){
            int p = atomicAdd(&s_cnt, 1);
            if (p < CBUF) ci[p] = blist[e >> 7]*128 + (e & 127);
        }
    }
    __syncthreads();
    int cnt = s_cnt < CBUF ? s_cnt : CBUF;

    // exact fp32 rescore: float4 loads, fmaf chain strictly k-ascending
    // (x,y,z,w in order == scalar chain bit-for-bit)
    for (int p = tid; p < cnt; p += 256){
        const float* __restrict__ xj = g_xn + (size_t)ci[p]*CD;
        float acc = 0.f;
        #pragma unroll 8
        for (int k4 = 0; k4 < CD/4; k4++){
            float4 v = ld4(xj + k4*4);
            acc = fmaf(xi[k4*4+0], v.x, acc);
            acc = fmaf(xi[k4*4+1], v.y, acc);
            acc = fmaf(xi[k4*4+2], v.z, acc);
            acc = fmaf(xi[k4*4+3], v.w, acc);
        }
        cv[p] = acc;
    }
    __syncthreads();

    // warp 0 selects top-20 by exact values (tie-break: lowest index)
    if (warp == 0){
        for (int sel = 0; sel < TOPK; sel++){
            float bv = -1e30f; int bi = 0x7fffffff; int bp = -1;
            for (int p = lane; p < cnt; p += 32){
                float vv = cv[p]; int ii = ci[p];
                if (vv > bv || (vv == bv && ii < bi)){ bv = vv; bi = ii; bp = p; }
            }
            #pragma unroll
            for (int off=16; off; off>>=1){
                float ov = __shfl_xor_sync(0xffffffffu, bv, off);
                int   oi = __shfl_xor_sync(0xffffffffu, bi, off);
                int   op = __shfl_xor_sync(0xffffffffu, bp, off);
                if (ov > bv || (ov == bv && oi < bi)){ bv = ov; bi = oi; bp = op; }
            }
            if (lane == 0){
                g_idx[(size_t)rowG*TOPK + sel] = bi;
                cv[bp] = -1e30f;
            }
            __syncwarp();
        }
    }
}

// ================= gather + relu + sum over 20 neighbors =================
__global__ __launch_bounds__(256) void gather_relu_sum_kernel(){
    const int i = blockIdx.x, c = threadIdx.x;
    __shared__ int nb[TOPK];
    if (c < TOPK) nb[c] = g_idx[(size_t)i*TOPK + c];
    __syncthreads();
    float a = g_Am[(size_t)i*CD + c];
    float acc = 0.f;
    #pragma unroll
    for (int k=0;k<TOPK;k++)
        acc += fmaxf(a + g_Bm[(size_t)nb[k]*CD + c], 0.f);
    g_R[(size_t)i*CD + c] = acc;
}

// ================= generic MLP GEMM =================
__global__ __launch_bounds__(256,2) void mlp_gemm_kernel(
    const float* __restrict__ A1, const float* __restrict__ A2,
    const float* __restrict__ W, int nslab,
    const float* __restrict__ bias, float biasScale,
    int doRelu, const float* __restrict__ res,
    float* __restrict__ Cout)
{
    __shared__ float As[2][16][132];
    __shared__ float Bs[2][16][132];
    const int tid = threadIdx.x;
    const int r0 = tid >> 2, kq = (tid & 3) << 2;
    const int kr0 = tid >> 5, nq = (tid & 31) << 2;
    const int tx = tid & 15, ty = tid >> 4;
    const int m0 = tx*8, n0 = ty*8;

    const size_t rowOff = (size_t)blockIdx.y*128*CD;
    const float* A1b = A1 + rowOff;
    const float* A2b = A2 ? (A2 + rowOff) : A1b;
    const float* Wb  = W + blockIdx.x*128;

    float acc[8][8];
    #pragma unroll
    for (int i=0;i<8;i++)
        #pragma unroll
        for (int j=0;j<8;j++) acc[i][j]=0.f;

    float4 va0 = ld4(A1b + r0*CD + kq);
    float4 va1 = ld4(A1b + (r0+64)*CD + kq);
    float4 vb0 = ld4(Wb + (size_t)kr0*CD + nq);
    float4 vb1 = ld4(Wb + (size_t)(kr0+8)*CD + nq);

    As[0][kq+0][r0]=va0.x; As[0][kq+1][r0]=va0.y; As[0][kq+2][r0]=va0.z; As[0][kq+3][r0]=va0.w;
    As[0][kq+0][r0+64]=va1.x; As[0][kq+1][r0+64]=va1.y; As[0][kq+2][r0+64]=va1.z; As[0][kq+3][r0+64]=va1.w;
    *(float4*)&Bs[0][kr0  ][nq] = vb0;
    *(float4*)&Bs[0][kr0+8][nq] = vb1;
    __syncthreads();

    int buf = 0;
    for (int s=0; s<nslab; s++){
        if (s+1 < nslab){
            int kk = (s+1)*16;
            const float* Ag = (kk < 256) ? (A1b + kk) : (A2b + (kk-256));
            va0 = ld4(Ag + r0*CD + kq);
            va1 = ld4(Ag + (r0+64)*CD + kq);
            vb0 = ld4(Wb + (size_t)(kk+kr0)*CD + nq);
            vb1 = ld4(Wb + (size_t)(kk+kr0+8)*CD + nq);
        }
        #pragma unroll
        for (int k=0;k<16;k++){
            float4 a0 = *(const float4*)&As[buf][k][m0];
            float4 a1 = *(const float4*)&As[buf][k][m0+4];
            float4 b0 = *(const float4*)&Bs[buf][k][n0];
            float4 b1 = *(const float4*)&Bs[buf][k][n0+4];
            float av[8] = {a0.x,a0.y,a0.z,a0.w,a1.x,a1.y,a1.z,a1.w};
            float bw[8] = {b0.x,b0.y,b0.z,b0.w,b1.x,b1.y,b1.z,b1.w};
            #pragma unroll
            for (int i=0;i<8;i++)
                #pragma unroll
                for (int j=0;j<8;j++)
                    acc[i][j] = fmaf(av[i], bw[j], acc[i][j]);
        }
        if (s+1 < nslab){
            int nb = buf ^ 1;
            As[nb][kq+0][r0]=va0.x; As[nb][kq+1][r0]=va0.y; As[nb][kq+2][r0]=va0.z; As[nb][kq+3][r0]=va0.w;
            As[nb][kq+0][r0+64]=va1.x; As[nb][kq+1][r0+64]=va1.y; As[nb][kq+2][r0+64]=va1.z; As[nb][kq+3][r0+64]=va1.w;
            *(float4*)&Bs[nb][kr0  ][nq] = vb0;
            *(float4*)&Bs[nb][kr0+8][nq] = vb1;
            __syncthreads();
            buf = nb;
        }
    }

    float bv_[8];
    if (bias){
        float4 t0 = ld4(bias + blockIdx.x*128 + n0);
        float4 t1 = ld4(bias + blockIdx.x*128 + n0 + 4);
        bv_[0]=t0.x*biasScale; bv_[1]=t0.y*biasScale; bv_[2]=t0.z*biasScale; bv_[3]=t0.w*biasScale;
        bv_[4]=t1.x*biasScale; bv_[5]=t1.y*biasScale; bv_[6]=t1.z*biasScale; bv_[7]=t1.w*biasScale;
    } else {
        #pragma unroll
        for (int j=0;j<8;j++) bv_[j]=0.f;
    }

    float* Cb = Cout + (size_t)blockIdx.y*128*CD + blockIdx.x*128;
    const float* Rb = res ? (res + (size_t)blockIdx.y*128*CD + blockIdx.x*128) : nullptr;
    #pragma unroll
    for (int i=0;i<8;i++){
        float o[8];
        #pragma unroll
        for (int j=0;j<8;j++){
            float t = acc[i][j] + bv_[j];
            if (doRelu) t = fmaxf(t, 0.f);
            o[j] = t;
        }
        if (Rb){
            float4 q0 = ld4(Rb + (size_t)(m0+i)*CD + n0);
            float4 q1 = ld4(Rb + (size_t)(m0+i)*CD + n0 + 4);
            o[0]+=q0.x; o[1]+=q0.y; o[2]+=q0.z; o[3]+=q0.w;
            o[4]+=q1.x; o[5]+=q1.y; o[6]+=q1.z; o[7]+=q1.w;
        }
        *(float4*)&Cb[(size_t)(m0+i)*CD + n0  ] = make_float4(o[0],o[1],o[2],o[3]);
        *(float4*)&Cb[(size_t)(m0+i)*CD + n0+4] = make_float4(o[4],o[5],o[6],o[7]);
    }
}

// ================= launch =================
extern "C" void kernel_launch(void* const* d_in, const int* in_sizes, int n_in,
                              void* d_out, int out_size)
{
    const float* x   = (const float*)d_in[0];
    const float* W1m = (const float*)d_in[1];
    const float* b1m = (const float*)d_in[2];
    const float* W2m = (const float*)d_in[3];
    const float* b2m = (const float*)d_in[4];
    const float* W1u = (const float*)d_in[5];
    const float* b1u = (const float*)d_in[6];
    const float* W2u = (const float*)d_in[7];
    const float* b2u = (const float*)d_in[8];
    float* out = (float*)d_out;

    float *p_Am=nullptr, *p_Bm=nullptr, *p_R=nullptr, *p_hagg=nullptr, *p_H=nullptr;
    cudaGetSymbolAddress((void**)&p_Am,   g_Am);
    cudaGetSymbolAddress((void**)&p_Bm,   g_Bm);
    cudaGetSymbolAddress((void**)&p_R,    g_R);
    cudaGetSymbolAddress((void**)&p_hagg, g_hagg);
    cudaGetSymbolAddress((void**)&p_H,    g_H);

    static cudaStream_t s2 = nullptr;
    static cudaEvent_t evSim[NCHUNK], evTk[NCHUNK], evFork;
    if (!s2){
        cudaStreamCreateWithFlags(&s2, cudaStreamNonBlocking);
        cudaEventCreateWithFlags(&evFork, cudaEventDisableTiming);
        for (int i = 0; i < NCHUNK; i++){
            cudaEventCreateWithFlags(&evSim[i], cudaEventDisableTiming);
            cudaEventCreateWithFlags(&evTk[i],  cudaEventDisableTiming);
        }
    }

    const int SIM_SMEM = 4 * BTILE * (int)sizeof(__nv_bfloat16);   // 73728 B
    cudaFuncSetAttribute(sim_mma_kernel, cudaFuncAttributeMaxDynamicSharedMemorySize, SIM_SMEM);

    cudaStream_t st = 0;

    rownorm_split_kernel<<<NPTS, 256, 0, st>>>(x);

    // fork s2
    cudaEventRecord(evFork, st);
    cudaStreamWaitEvent(s2, evFork, 0);

    // A_msg / B_msg on s2 (overlap with sim)
    mlp_gemm_kernel<<<dim3(2,128), 256, 0, s2>>>(x, nullptr, W1m,          16, b1m, 1.f, 0, nullptr, p_Am);
    mlp_gemm_kernel<<<dim3(2,128), 256, 0, s2>>>(x, nullptr, W1m + 256*CD, 16, nullptr, 0.f, 0, nullptr, p_Bm);

    // band-ordered symmetric sim (st) + per-band topk (s2)
    for (int c = 0; c < NCHUNK; c++){
        const int cBase = c * 16;                 // tile-row offset (128-row tiles)
        const int gw = 128 - cBase;               // J range width
        sim_mma_kernel<<<dim3(gw, 16), 256, SIM_SMEM, st>>>(cBase);
        cudaEventRecord(evSim[c], st);
        cudaStreamWaitEvent(s2, evSim[c], 0);
        topk_kernel<<<CHUNK, 256, 0, s2>>>(c*CHUNK);
        cudaEventRecord(evTk[c], s2);
    }
    cudaStreamWaitEvent(st, evTk[NCHUNK-1], 0);

    // R_i = sum_j relu(A_i + B_j)
    gather_relu_sum_kernel<<<NPTS, 256, 0, st>>>();

    // h_agg = R @ W2_msg + 20*b2_msg
    mlp_gemm_kernel<<<dim3(2,128), 256, 0, st>>>(p_R, nullptr, W2m, 16, b2m, (float)TOPK, 0, nullptr, p_hagg);

    // H = relu(x @ W1u[0:256] + h_agg @ W1u[256:512] + b1u)
    mlp_gemm_kernel<<<dim3(2,128), 256, 0, st>>>(x, p_hagg, W1u, 32, b1u, 1.f, 1, nullptr, p_H);

    // out = x + H @ W2_upd + b2_upd
    mlp_gemm_kernel<<<dim3(2,128), 256, 0, st>>>(p_H, nullptr, W2u, 16, b2u, 1.f, 0, x, out);
}